// round 16
// baseline (speedup 1.0000x reference)
#include <cuda_runtime.h>
#include <cuda_bf16.h>
#include <cstdint>

// LinearMPC via mma.sync bf16 split hi/lo.
// u <- clip(u - s(uH + f)), 100 iters, B=2048, M=512, H symmetric.
// R16: cluster-of-2 n-split. Pair shares 32 batches; each CTA computes 256
// output cols -> H L2 traffic halves vs R15. H fragment-ordered (coalesced
// LDG.128, register ring). u exchanged via gmem packed words with split
// cluster barrier: own-half chunks overlap the peer-half exchange.

#define MD 512
#define BATCH 2048
#define BT 32              // batches per cluster pair
#define ITERS 100
#define STEPC 0.01f
#define THREADS 256
#define USTR 2080u         // u_s row stride bytes (520 words)
#define FSTR 1056u         // f_s row stride bytes (264 words)
#define F_OFF 66560u       // f_s offset = 32*USTR
#define SMEM_TOTAL 100352  // F_OFF + 32*FSTR

__device__ __align__(16) float    g_f [BATCH * MD];
__device__ __align__(16) uint32_t g_up[BATCH * MD];   // packed (hi<<16)|lo u
// Fragment-ordered packed H: idx (((mb*32 + kc)*4 + mf)*32 + lane), uint4.
// lane(qr,qc) holds { H[r][k0], H[r][k0+1], H[r][k0+8], H[r][k0+9] },
// r = mb*32+mf*8+qr, k0 = kc*16+2*qc, word = (bf16hi<<16)|bf16lo.
__device__ __align__(16) uint4 g_hb[MD / 32 * 32 * 4 * 32];   // 65536 uint4

__device__ __forceinline__ uint32_t prmt(uint32_t a, uint32_t b, uint32_t s) {
    uint32_t d;
    asm("prmt.b32 %0, %1, %2, %3;" : "=r"(d) : "r"(a), "r"(b), "r"(s));
    return d;
}
__device__ __forceinline__ void mma4(float* d, const uint32_t* a,
                                     const uint32_t* b) {
    asm volatile(
        "mma.sync.aligned.m16n8k16.row.col.f32.bf16.bf16.f32 "
        "{%0,%1,%2,%3}, {%4,%5,%6,%7}, {%8,%9}, {%0,%1,%2,%3};"
        : "+f"(d[0]), "+f"(d[1]), "+f"(d[2]), "+f"(d[3])
        : "r"(a[0]), "r"(a[1]), "r"(a[2]), "r"(a[3]), "r"(b[0]), "r"(b[1]));
}
__device__ __forceinline__ float clamp1(float x) {
    return fminf(fmaxf(x, -1.0f), 1.0f);
}
__device__ __forceinline__ uint32_t pack_u(float v) {
    __nv_bfloat16 h = __float2bfloat16(v);
    __nv_bfloat16 l = __float2bfloat16(v - __bfloat162float(h));
    return ((uint32_t)__bfloat16_as_ushort(h) << 16)
         | (uint32_t)__bfloat16_as_ushort(l);
}
__device__ __forceinline__ float dec(uint32_t w) {
    return __bfloat162float(__ushort_as_bfloat16((unsigned short)(w >> 16)))
         + __bfloat162float(__ushort_as_bfloat16((unsigned short)(w & 0xFFFFu)));
}

// Prologue 1: f[b, k*8+i] = -2 * Phi[k] @ Q @ (xref[b,k] - xref[b,0])
__global__ void mpc_f_kernel(const float* __restrict__ xref,
                             const float* __restrict__ Phi,
                             const float* __restrict__ Q) {
    __shared__ float sPhi[64 * 64];
    __shared__ float sQ[64];
    for (int i = threadIdx.x; i < 4096; i += 256) sPhi[i] = Phi[i];
    if (threadIdx.x < 64) sQ[threadIdx.x] = Q[threadIdx.x];
    __syncthreads();

    int k = threadIdx.x & 63;
    int b = blockIdx.x * 4 + (threadIdx.x >> 6);
    const float* xr = xref + (size_t)b * 65 * 8;
    float dx[8], t[8];
#pragma unroll
    for (int l = 0; l < 8; l++) dx[l] = xr[k * 8 + l] - xr[l];
#pragma unroll
    for (int j = 0; j < 8; j++) {
        float s = 0.f;
#pragma unroll
        for (int l = 0; l < 8; l++) s = fmaf(sQ[j * 8 + l], dx[l], s);
        t[j] = s;
    }
    const float* Pk = sPhi + k * 64;
#pragma unroll
    for (int i = 0; i < 8; i++) {
        float s = 0.f;
#pragma unroll
        for (int j = 0; j < 8; j++) s = fmaf(Pk[i * 8 + j], t[j], s);
        g_f[(size_t)b * MD + k * 8 + i] = -2.0f * s;
    }
}

// Prologue 2: pack+permute H into fragment-ordered g_hb (65536 threads).
__global__ void mpc_hpack_kernel(const float* __restrict__ Hm) {
    int idx = blockIdx.x * 256 + threadIdx.x;        // 0..65535
    int lane = idx & 31;
    int mf   = (idx >> 5) & 3;
    int kc   = (idx >> 7) & 31;
    int mb   = idx >> 12;
    int qr = lane >> 2, qc = lane & 3;
    int row = mb * 32 + mf * 8 + qr;
    int k0  = kc * 16 + 2 * qc;
    const float* hr = Hm + (size_t)row * MD + k0;
    uint4 v;
    v.x = pack_u(hr[0]);
    v.y = pack_u(hr[1]);
    v.z = pack_u(hr[8]);
    v.w = pack_u(hr[9]);
    g_hb[idx] = v;
}

// H-fragment prefetch: 4 coalesced LDG.128 (mf stride 32 uint4).
#define PREFETCH(BUF, KC_)                                                    \
    {                                                                         \
        const uint4* p_ = hb_base + (uint32_t)(((KC_) & 31) * 128);           \
        _Pragma("unroll")                                                     \
        for (int i_ = 0; i_ < 4; i_++) BUF[i_] = __ldg(p_ + i_ * 32);         \
    }

// One 16-k chunk: A (u, packed SMEM, 2 batch-frags) x B (regs, 4 mf) = 24 MMAs.
#define COMPUTE(BUF, KC_)                                                     \
    {                                                                         \
        const uint32_t ub_ = uAb + (uint32_t)((KC_) & 31) * 64u;              \
        uint32_t ah[2][4], al[2][4];                                          \
        _Pragma("unroll")                                                     \
        for (int bf_ = 0; bf_ < 2; bf_++) {                                   \
            const uint32_t b_ = ub_ + (uint32_t)bf_ * (16u * USTR);           \
            uint2 wa0 = *(const uint2*)(smem + b_);                           \
            uint2 wa2 = *(const uint2*)(smem + b_ + 32u);                     \
            uint2 wa1 = *(const uint2*)(smem + b_ + 8u * USTR);               \
            uint2 wa3 = *(const uint2*)(smem + b_ + 8u * USTR + 32u);         \
            ah[bf_][0] = prmt(wa0.x, wa0.y, 0x7632u);                         \
            al[bf_][0] = prmt(wa0.x, wa0.y, 0x5410u);                         \
            ah[bf_][1] = prmt(wa1.x, wa1.y, 0x7632u);                         \
            al[bf_][1] = prmt(wa1.x, wa1.y, 0x5410u);                         \
            ah[bf_][2] = prmt(wa2.x, wa2.y, 0x7632u);                         \
            al[bf_][2] = prmt(wa2.x, wa2.y, 0x5410u);                         \
            ah[bf_][3] = prmt(wa3.x, wa3.y, 0x7632u);                         \
            al[bf_][3] = prmt(wa3.x, wa3.y, 0x5410u);                         \
        }                                                                     \
        _Pragma("unroll")                                                     \
        for (int mf_ = 0; mf_ < 4; mf_++) {                                   \
            uint32_t bh[2], bl[2];                                            \
            bh[0] = prmt(BUF[mf_].x, BUF[mf_].y, 0x7632u);                    \
            bl[0] = prmt(BUF[mf_].x, BUF[mf_].y, 0x5410u);                    \
            bh[1] = prmt(BUF[mf_].z, BUF[mf_].w, 0x7632u);                    \
            bl[1] = prmt(BUF[mf_].z, BUF[mf_].w, 0x5410u);                    \
            _Pragma("unroll")                                                 \
            for (int bf_ = 0; bf_ < 2; bf_++) {                               \
                float* d_ = acc[bf_][mf_];                                    \
                mma4(d_, ah[bf_], bh);                                        \
                mma4(d_, al[bf_], bh);                                        \
                mma4(d_, ah[bf_], bl);                                        \
            }                                                                 \
        }                                                                     \
    }

__global__ void __launch_bounds__(THREADS, 1)
mpc_mma_kernel(float* __restrict__ out) {
    extern __shared__ char smem[];   // u_s [32][520w] @0; f_s [32][264w] @F_OFF
    const int tid = threadIdx.x, lane = tid & 31;
    const int qr = lane >> 2, qc = lane & 3;
    const int w = tid >> 5;
    uint32_t rank;
    asm("mov.u32 %0, %%cluster_ctarank;" : "=r"(rank));
    const int cb = (int)(blockIdx.x >> 1) * BT;      // 32 batches per pair
    const int n0 = (int)rank * 256;                  // own 256-col half
    const int mb = (int)rank * 8 + w;                // warp's 32-row H block
    const int start = (int)rank * 16;                // own-half first chunk

    // Stage f (own cols only).
    for (int i = tid; i < BT * 256; i += THREADS) {
        int r = i >> 8, c = i & 255;
        *(float*)(smem + F_OFF + (uint32_t)r * FSTR + (uint32_t)c * 4u) =
            g_f[(size_t)(cb + r) * MD + n0 + c];
    }
    __syncthreads();

    // Per-lane constants.
    const uint4* hb_base = g_hb + ((uint32_t)mb * 4096u + (uint32_t)lane);
    const uint32_t uAb = (uint32_t)qr * USTR + 8u * qc;
    const int lc = w * 32 + 2 * qc;                  // local col base (mf adds 8*mf)

    // Iteration 0: u1 = clip(-s*f) for own cols -> u_s + g_up.
#pragma unroll
    for (int bf = 0; bf < 2; bf++) {
        uint32_t fr = F_OFF + (uint32_t)(16 * bf + qr) * FSTR;
        uint32_t ur = (uint32_t)(16 * bf + qr) * USTR;
#pragma unroll
        for (int mf = 0; mf < 4; mf++) {
            int c = lc + 8 * mf;
            float2 f0 = *(float2*)(smem + fr + c * 4);
            float2 f1 = *(float2*)(smem + fr + 8 * FSTR + c * 4);
            uint2 p0 = make_uint2(pack_u(clamp1(-STEPC * f0.x)),
                                  pack_u(clamp1(-STEPC * f0.y)));
            uint2 p1 = make_uint2(pack_u(clamp1(-STEPC * f1.x)),
                                  pack_u(clamp1(-STEPC * f1.y)));
            *(uint2*)(smem + ur + (n0 + c) * 4) = p0;
            *(uint2*)(smem + ur + 8 * USTR + (n0 + c) * 4) = p1;
            __stcg((uint2*)(g_up + (size_t)(cb + 16 * bf + qr) * MD + n0 + c), p0);
            __stcg((uint2*)(g_up + (size_t)(cb + 16 * bf + qr + 8) * MD + n0 + c), p1);
        }
    }
    __syncthreads();

    // Peer-exchange geometry: row = tid/8, 8 threads x 8 uint4 per 1KB row.
    const int prow = tid >> 3, pcg = tid & 7;
    const uint32_t pw0 = (uint32_t)(rank ^ 1u) * 256u;   // peer col word base
    const uint32_t* pg = g_up + (size_t)(cb + prow) * MD + pw0 + pcg * 4;
    char* ps = smem + (uint32_t)prow * USTR + (pw0 + pcg * 4u) * 4u;

    uint4 B0[4], B1[4];
    PREFETCH(B0, start);
    PREFETCH(B1, start + 1);

    for (int it = 1; it < ITERS; it++) {
        asm volatile("barrier.cluster.arrive.aligned;" ::: "memory");  // release u

        float acc[2][4][4];
#pragma unroll
        for (int bf = 0; bf < 2; bf++) {
            uint32_t fr = F_OFF + (uint32_t)(16 * bf + qr) * FSTR;
#pragma unroll
            for (int mf = 0; mf < 4; mf++) {
                int c = lc + 8 * mf;
                float2 f0 = *(float2*)(smem + fr + c * 4);
                float2 f1 = *(float2*)(smem + fr + 8 * FSTR + c * 4);
                acc[bf][mf][0] = f0.x; acc[bf][mf][1] = f0.y;
                acc[bf][mf][2] = f1.x; acc[bf][mf][3] = f1.y;
            }
        }

        // Own-half chunks (u available locally; overlaps peer's update/store).
#pragma unroll 1
        for (int j = 0; j < 16; j += 2) {
            COMPUTE(B0, start + j);
            PREFETCH(B0, start + j + 2);
            COMPUTE(B1, start + j + 1);
            PREFETCH(B1, start + j + 3);
        }

        // Acquire peer's u, stage into u_s peer half.
        asm volatile("barrier.cluster.wait.aligned;" ::: "memory");
        {
            uint4 t0[8];
#pragma unroll
            for (int j = 0; j < 8; j++)
                t0[j] = __ldcg((const uint4*)(pg + j * 32));
#pragma unroll
            for (int j = 0; j < 8; j++)
                *(uint4*)(ps + j * 128) = t0[j];
        }
        __syncthreads();

        // Peer-half chunks.
#pragma unroll 1
        for (int j = 16; j < 32; j += 2) {
            COMPUTE(B0, start + j);
            PREFETCH(B0, start + j + 2);   // wraps to next iteration's chunks
            COMPUTE(B1, start + j + 1);
            PREFETCH(B1, start + j + 3);
        }

        // Update own cols: u <- clip(u - s*acc)   (acc already includes f).
        const bool last = (it == ITERS - 1);
#pragma unroll
        for (int bf = 0; bf < 2; bf++) {
            uint32_t ur = (uint32_t)(16 * bf + qr) * USTR;
#pragma unroll
            for (int mf = 0; mf < 4; mf++) {
                int c = lc + 8 * mf;
                uint2 w0 = *(uint2*)(smem + ur + (n0 + c) * 4);
                uint2 w1 = *(uint2*)(smem + ur + 8 * USTR + (n0 + c) * 4);
                float v0 = clamp1(fmaf(-STEPC, acc[bf][mf][0], dec(w0.x)));
                float v1 = clamp1(fmaf(-STEPC, acc[bf][mf][1], dec(w0.y)));
                float v2 = clamp1(fmaf(-STEPC, acc[bf][mf][2], dec(w1.x)));
                float v3 = clamp1(fmaf(-STEPC, acc[bf][mf][3], dec(w1.y)));
                if (last) {
                    *(float2*)&out[(size_t)(cb + 16 * bf + qr) * MD + n0 + c] =
                        make_float2(v0, v1);
                    *(float2*)&out[(size_t)(cb + 16 * bf + qr + 8) * MD + n0 + c] =
                        make_float2(v2, v3);
                } else {
                    uint2 p0 = make_uint2(pack_u(v0), pack_u(v1));
                    uint2 p1 = make_uint2(pack_u(v2), pack_u(v3));
                    *(uint2*)(smem + ur + (n0 + c) * 4) = p0;
                    *(uint2*)(smem + ur + 8 * USTR + (n0 + c) * 4) = p1;
                    __stcg((uint2*)(g_up + (size_t)(cb + 16 * bf + qr) * MD + n0 + c), p0);
                    __stcg((uint2*)(g_up + (size_t)(cb + 16 * bf + qr + 8) * MD + n0 + c), p1);
                }
            }
        }
        __syncthreads();   // own-half u_s consistent before next own-chunks
    }
}

extern "C" void kernel_launch(void* const* d_in, const int* in_sizes, int n_in,
                              void* d_out, int out_size) {
    // metadata order: x0, xref, H, Phi, Q
    const float* xref = (const float*)d_in[1];
    const float* H    = (const float*)d_in[2];
    const float* Phi  = (const float*)d_in[3];
    const float* Q    = (const float*)d_in[4];
    float* out        = (float*)d_out;

    cudaFuncSetAttribute(mpc_mma_kernel,
                         cudaFuncAttributeMaxDynamicSharedMemorySize, SMEM_TOTAL);

    mpc_f_kernel<<<BATCH / 4, 256>>>(xref, Phi, Q);
    mpc_hpack_kernel<<<MD * MD / 4 / 256, 256>>>(H);

    cudaLaunchConfig_t cfg = {};
    cfg.gridDim = dim3((BATCH / BT) * 2, 1, 1);   // 128 CTAs, 64 pairs
    cfg.blockDim = dim3(THREADS, 1, 1);
    cfg.dynamicSmemBytes = SMEM_TOTAL;
    cudaLaunchAttribute attrs[1];
    attrs[0].id = cudaLaunchAttributeClusterDimension;
    attrs[0].val.clusterDim.x = 2;
    attrs[0].val.clusterDim.y = 1;
    attrs[0].val.clusterDim.z = 1;
    cfg.attrs = attrs;
    cfg.numAttrs = 1;
    cudaLaunchKernelEx(&cfg, mpc_mma_kernel, out);
}